// round 1
// baseline (speedup 1.0000x reference)
#include <cuda_runtime.h>
#include <math.h>

#define PI_F 3.14159274101257324f   // float32(pi)
#define H 512
#define W 512
#define NIMG 32                      // 16 pred + 16 tgt
#define NBINS 24                     // 3 radial * 8 angle

// ---- scratch (static device globals; no allocations allowed) ----
__device__ float2 d_scratch[(size_t)NIMG * H * W];   // 64 MB: row-FFT output, transposed
__device__ float  d_sums[NIMG * NBINS];
__device__ int    d_counts[NBINS];
__device__ unsigned char d_binmap[H * W];            // bin id per (k_row,k_col) unshifted; 255 = none

// float32 linspace(-1, 1, 512) as numpy/jax computes it: i*step + start
__device__ __forceinline__ float lin512(int i) {
    const float step = 2.0f / 511.0f;
    return (float)i * step + (-1.0f);
}

__device__ __forceinline__ float hann512(int n) {
    // 0.5*(1 - cos(2*pi*n/511)) with jnp's op order: (2pi * n) / 511
    return 0.5f * (1.0f - cosf((6.283185307179586f * (float)n) / 511.0f));
}

// ---------------- init ----------------
__global__ void k_init() {
    int t = threadIdx.x;
    if (t < NIMG * NBINS) d_sums[t] = 0.0f;
    if (t < NBINS) d_counts[t] = 0;
}

// ---------------- polar bin map ----------------
__global__ void k_binmap() {
    int u = blockIdx.x;     // unshifted freq row
    int v = threadIdx.x;    // unshifted freq col
    __shared__ int cnt[NBINS];
    if (v < NBINS) cnt[v] = 0;
    __syncthreads();

    // fftshifted coordinates
    int i = (u + H / 2) & (H - 1);
    int j = (v + W / 2) & (W - 1);
    float yv = lin512(i);
    float xv = lin512(j);

    float rad = sqrtf(xv * xv + yv * yv) / sqrtf(2.0f);  // grid max is at (-1,-1) corner

    float a = atan2f(yv, xv);
    a = fmodf(a, PI_F);
    if (a < 0.0f) a += PI_F;

    // radial edges: linspace(0.08, 0.9, 4) -> i*step + 0.08, last = 0.9
    const float rstep = (0.9f - 0.08f) / 3.0f;
    float re0 = 0.08f;
    float re1 = 1.0f * rstep + 0.08f;
    float re2 = 2.0f * rstep + 0.08f;
    float re3 = 0.9f;
    int rb = -1;
    if (rad >= re0 && rad < re1) rb = 0;
    else if (rad >= re1 && rad < re2) rb = 1;
    else if (rad >= re2 && rad <= re3) rb = 2;

    // angle edges: linspace(0, pi, 9) -> k*(pi/8), last = pi; last bin inclusive
    const float astep = PI_F / 8.0f;
    int ab = 7;
    #pragma unroll
    for (int k = 0; k < 7; k++) {
        float e0 = (float)k * astep;
        float e1 = (float)(k + 1) * astep;
        if (a >= e0 && a < e1) { ab = k; break; }
    }

    unsigned char bin = 255;
    if (rb >= 0) bin = (unsigned char)(rb * 8 + ab);
    d_binmap[u * W + v] = bin;

    if (bin < NBINS) atomicAdd(&cnt[bin], 1);
    __syncthreads();
    if (v < NBINS && cnt[v] > 0) atomicAdd(&d_counts[v], cnt[v]);
}

// ---------------- shared-memory 512-pt radix-2 DIT FFT helpers ----------------
__device__ __forceinline__ void fft512(float2* sh, const float2* tw, int t) {
    #pragma unroll
    for (int s = 0; s < 9; s++) {
        int half = 1 << s;
        int j = t & (half - 1);
        int base = ((t >> s) << (s + 1)) | j;
        float2 w = tw[j << (8 - s)];
        float2 u = sh[base];
        float2 v = sh[base + half];
        float2 vw = make_float2(v.x * w.x - v.y * w.y, v.x * w.y + v.y * w.x);
        sh[base]        = make_float2(u.x + vw.x, u.y + vw.y);
        sh[base + half] = make_float2(u.x - vw.x, u.y - vw.y);
        __syncthreads();
    }
}

// ---------------- row FFT: luma * hann, FFT along W, write transposed ----------------
__global__ void k_rowfft(const float* __restrict__ pred, const float* __restrict__ tgt) {
    const int row = blockIdx.x;
    const int img = blockIdx.y;
    const int t = threadIdx.x;   // 0..255

    __shared__ float2 sh[512];
    __shared__ float2 tw[256];
    {
        float s, c;
        sincosf(-6.283185307179586f * (float)t / 512.0f, &s, &c);
        tw[t] = make_float2(c, s);
    }

    const float* base = (img < 16)
        ? pred + (size_t)img * 3 * H * W
        : tgt  + (size_t)(img - 16) * 3 * H * W;

    float wr = hann512(row);
    int r0 = __brev((unsigned)t) >> 23;   // 9-bit bit-reverse (t<256 -> even r0)

    #pragma unroll
    for (int k = 0; k < 2; k++) {
        int col = t + k * 256;
        const float* p = base + (size_t)row * W + col;
        float lum = 0.2989f * p[0] + 0.587f * p[H * W] + 0.114f * p[2 * H * W];
        float wc = hann512(col);
        sh[r0 + k] = make_float2(lum * wr * wc, 0.0f);
    }
    __syncthreads();

    fft512(sh, tw, t);

    float2* dst = d_scratch + (size_t)img * H * W;
    dst[(size_t)t * H + row]         = sh[t];
    dst[(size_t)(t + 256) * H + row] = sh[t + 256];
}

// ---------------- column FFT + log-magnitude + bin accumulation ----------------
__global__ void k_colfft() {
    const int kcol = blockIdx.x;
    const int img  = blockIdx.y;
    const int t = threadIdx.x;   // 0..255

    __shared__ float2 sh[512];
    __shared__ float2 tw[256];
    __shared__ float acc[NBINS];
    if (t < NBINS) acc[t] = 0.0f;
    {
        float s, c;
        sincosf(-6.283185307179586f * (float)t / 512.0f, &s, &c);
        tw[t] = make_float2(c, s);
    }

    const float2* src = d_scratch + (size_t)img * H * W + (size_t)kcol * H;
    int r0 = __brev((unsigned)t) >> 23;
    sh[r0]     = src[t];
    sh[r0 + 1] = src[t + 256];
    __syncthreads();

    fft512(sh, tw, t);

    #pragma unroll
    for (int kk = 0; kk < 2; kk++) {
        int krow = t + kk * 256;
        float2 f = sh[krow];
        float mag = log1pf(sqrtf(f.x * f.x + f.y * f.y));
        unsigned char bin = d_binmap[krow * W + kcol];
        if (bin < NBINS) atomicAdd(&acc[bin], mag);
    }
    __syncthreads();
    if (t < NBINS) atomicAdd(&d_sums[img * NBINS + t], acc[t]);
}

// ---------------- finalize: energies, normalization, charbonnier, weighted mean ----------------
__global__ void k_final(const float* __restrict__ rw, float* __restrict__ out) {
    const int t = threadIdx.x;  // 768 threads
    __shared__ float e[NIMG * NBINS];     // 768
    __shared__ float denom[NIMG * 3];     // 96
    __shared__ float red[NIMG * NBINS];   // 768

    {
        float c = (float)d_counts[t % NBINS];
        e[t] = d_sums[t] / fmaxf(c, 1e-6f);
    }
    __syncthreads();

    if (t < NIMG * 3) {
        int img = t / 3, r = t % 3;
        float s = 0.0f;
        #pragma unroll
        for (int a = 0; a < 8; a++) s += e[img * NBINS + r * 8 + a];
        denom[t] = fmaxf(s, 1e-6f);
    }
    __syncthreads();

    float term = 0.0f;
    if (t < 16 * NBINS) {
        int b = t / NBINS, rest = t % NBINS, r = rest / 8;
        float pe = e[b * NBINS + rest]        / denom[b * 3 + r];
        float te = e[(16 + b) * NBINS + rest] / denom[(16 + b) * 3 + r];
        float d = pe - te;
        term = sqrtf(d * d + 1e-6f) * rw[r];
    }
    red[t] = term;
    __syncthreads();

    for (int off = 384; off > 2; off >>= 1) {
        if (t < off) red[t] += red[t + off];
        __syncthreads();
    }
    if (t == 0) out[0] = (red[0] + red[1] + red[2]) / 384.0f;
}

// ---------------- launcher ----------------
extern "C" void kernel_launch(void* const* d_in, const int* in_sizes, int n_in,
                              void* d_out, int out_size) {
    const float* pred = (const float*)d_in[0];
    const float* tgt  = (const float*)d_in[1];
    const float* rw   = (const float*)d_in[2];
    float* out = (float*)d_out;

    k_init<<<1, 1024>>>();
    k_binmap<<<H, W>>>();
    k_rowfft<<<dim3(H, NIMG), 256>>>(pred, tgt);
    k_colfft<<<dim3(W, NIMG), 256>>>();
    k_final<<<1, NIMG * NBINS>>>(rw, out);
}

// round 2
// speedup vs baseline: 3.2801x; 3.2801x over previous
#include <cuda_runtime.h>
#include <math.h>

#define PI_F 3.14159274101257324f   // float32(pi)
#define H 512
#define W 512
#define NIMG 32                      // 16 pred + 16 tgt
#define NBINS 24                     // 3 radial * 8 angle
#define KCOLS 257                    // Hermitian: only cols 0..256 stored

// ---- scratch (static device globals; no allocations allowed) ----
__device__ float2 d_scratch[(size_t)NIMG * KCOLS * H];   // [img][kcol][row], 33.7 MB
__device__ float  d_sums[NIMG * NBINS];
__device__ int    d_counts[NBINS];
__device__ unsigned char d_binmapT[W * H];               // [v][u], transposed bin map

// float32 linspace(-1, 1, 512) as numpy/jax computes it: i*step + start
__device__ __forceinline__ float lin512(int i) {
    const float step = 2.0f / 511.0f;
    return (float)i * step + (-1.0f);
}
__device__ __forceinline__ float hann512(int n) {
    return 0.5f * (1.0f - cosf((6.283185307179586f * (float)n) / 511.0f));
}

// ---------------- complex helpers ----------------
__device__ __forceinline__ float2 cadd(float2 a, float2 b){return make_float2(a.x+b.x,a.y+b.y);}
__device__ __forceinline__ float2 csub(float2 a, float2 b){return make_float2(a.x-b.x,a.y-b.y);}
__device__ __forceinline__ float2 cmul(float2 a, float2 b){return make_float2(a.x*b.x-a.y*b.y, a.x*b.y+a.y*b.x);}
__device__ __forceinline__ float2 mulmj(float2 a){return make_float2(a.y,-a.x);} // * (-i)

// 8-point DFT in registers (DIF, result reordered to natural frequency order)
__device__ __forceinline__ void fft8(float2 r[8]) {
    const float C = 0.70710678118654752f;
    float2 u0=cadd(r[0],r[4]), u4=csub(r[0],r[4]);
    float2 u1=cadd(r[1],r[5]), u5=csub(r[1],r[5]);
    float2 u2=cadd(r[2],r[6]), u6=csub(r[2],r[6]);
    float2 u3=cadd(r[3],r[7]), u7=csub(r[3],r[7]);
    u5 = make_float2(C*(u5.x+u5.y), C*(u5.y-u5.x));      // * W8^1
    u6 = mulmj(u6);                                      // * W8^2
    u7 = make_float2(C*(u7.y-u7.x), -C*(u7.x+u7.y));     // * W8^3
    float2 v0=cadd(u0,u2), v2=csub(u0,u2);
    float2 v1=cadd(u1,u3), v3=mulmj(csub(u1,u3));
    float2 v4=cadd(u4,u6), v6=csub(u4,u6);
    float2 v5=cadd(u5,u7), v7=mulmj(csub(u5,u7));
    r[0]=cadd(v0,v1); r[4]=csub(v0,v1);
    r[2]=cadd(v2,v3); r[6]=csub(v2,v3);
    r[1]=cadd(v4,v5); r[5]=csub(v4,v5);
    r[3]=cadd(v6,v7); r[7]=csub(v6,v7);
}

#define PAD1 72   // exchange-1 row stride (floats): conflict-free
#define PAD2 66   // exchange-2 row stride (floats): <=2-way
#define SBUF 584  // per-slot buffer size (floats), >= 512 natural & padded use

// 512-pt FFT: 64 threads (tl), 8 values/thread. Input r[j] = x[tl + 64*j].
// Output: r[k2] = X[k0 + 8*k1 + 64*k2] with k0 = tl>>3, k1 = tl&7.
// Uses block-wide __syncthreads (all slots in block must call together).
__device__ __forceinline__ void fft512(float2 r[8], float* sre, float* sim, int tl) {
    // stage 1: DFT over j -> k0, twiddle W512^{tl*k0}
    fft8(r);
    float s, c;
    __sincosf(-6.283185307179586f * (float)tl / 512.0f, &s, &c);
    float2 w = make_float2(c, s), wk = w;
    #pragma unroll
    for (int k = 1; k < 8; k++) { r[k] = cmul(r[k], wk); wk = cmul(wk, w); }
    // exchange 1: sh[k0*PAD1 + m], m = tl
    #pragma unroll
    for (int k = 0; k < 8; k++) { sre[k*PAD1 + tl] = r[k].x; sim[k*PAD1 + tl] = r[k].y; }
    __syncthreads();
    int k0 = tl >> 3, m0 = tl & 7;
    #pragma unroll
    for (int m1 = 0; m1 < 8; m1++) {
        int a = k0*PAD1 + m0 + 8*m1;
        r[m1] = make_float2(sre[a], sim[a]);
    }
    // stage 2: DFT over m1 -> k1, twiddle W64^{m0*k1}
    fft8(r);
    __sincosf(-6.283185307179586f * (float)m0 / 64.0f, &s, &c);
    w = make_float2(c, s); wk = w;
    #pragma unroll
    for (int k = 1; k < 8; k++) { r[k] = cmul(r[k], wk); wk = cmul(wk, w); }
    __syncthreads();
    // exchange 2: sh[k0*PAD2 + k1*8 + m0]
    #pragma unroll
    for (int k = 0; k < 8; k++) { sre[k0*PAD2 + k*8 + m0] = r[k].x; sim[k0*PAD2 + k*8 + m0] = r[k].y; }
    __syncthreads();
    int k1 = tl & 7;
    #pragma unroll
    for (int m = 0; m < 8; m++) {
        int a = k0*PAD2 + k1*8 + m;
        r[m] = make_float2(sre[a], sim[a]);
    }
    // stage 3: DFT over m0 -> k2 (no twiddle)
    fft8(r);
}

// ---------------- init ----------------
__global__ void k_init() {
    int t = threadIdx.x;
    if (t < NIMG * NBINS) d_sums[t] = 0.0f;
    if (t < NBINS) d_counts[t] = 0;
}

// ---------------- polar bin map (transposed) + counts ----------------
__global__ void k_binmap() {
    int v = blockIdx.x;    // unshifted freq col
    int u = threadIdx.x;   // unshifted freq row
    __shared__ int cnt[NBINS];
    if (u < NBINS) cnt[u] = 0;
    __syncthreads();

    int i = (u + H/2) & (H - 1);
    int j = (v + W/2) & (W - 1);
    float yv = lin512(i);
    float xv = lin512(j);

    float rad = sqrtf(xv*xv + yv*yv) / sqrtf(2.0f);
    float a = atan2f(yv, xv);
    a = fmodf(a, PI_F);
    if (a < 0.0f) a += PI_F;

    const float rstep = (0.9f - 0.08f) / 3.0f;
    float re1 = 1.0f * rstep + 0.08f;
    float re2 = 2.0f * rstep + 0.08f;
    int rb = -1;
    if (rad >= 0.08f && rad < re1) rb = 0;
    else if (rad >= re1 && rad < re2) rb = 1;
    else if (rad >= re2 && rad <= 0.9f) rb = 2;

    const float astep = PI_F / 8.0f;
    int ab = 7;
    #pragma unroll
    for (int k = 0; k < 7; k++) {
        float e0 = (float)k * astep;
        float e1 = (float)(k+1) * astep;
        if (a >= e0 && a < e1) { ab = k; break; }
    }

    unsigned char bin = 255;
    if (rb >= 0) bin = (unsigned char)(rb * 8 + ab);
    d_binmapT[v * H + u] = bin;

    if (bin < NBINS) atomicAdd(&cnt[bin], 1);
    __syncthreads();
    if (u < NBINS && cnt[u] > 0) atomicAdd(&d_counts[u], cnt[u]);
}

// ---------------- row pass: 2 real rows per complex FFT, unpack, transposed write ----
// grid (64, 32), block 256: 4 FFT slots, slot f handles rows rg*8+2f, rg*8+2f+1
__global__ void __launch_bounds__(256) k_rowfft(const float* __restrict__ pred,
                                                const float* __restrict__ tgt) {
    __shared__ float s_re[4][SBUF];
    __shared__ float s_im[4][SBUF];

    const int tid = threadIdx.x;
    const int f  = tid >> 6;
    const int tl = tid & 63;
    const int rg  = blockIdx.x;   // row group (8 rows)
    const int img = blockIdx.y;

    const float* base = (img < 16)
        ? pred + (size_t)img * 3 * H * W
        : tgt  + (size_t)(img - 16) * 3 * H * W;

    const int rA = rg * 8 + 2 * f;
    const int rB = rA + 1;
    const float wrA = hann512(rA);
    const float wrB = hann512(rB);

    float2 r[8];
    #pragma unroll
    for (int j = 0; j < 8; j++) {
        int col = tl + 64 * j;
        const float* pA = base + (size_t)rA * W + col;
        const float* pB = base + (size_t)rB * W + col;
        float lA = 0.2989f*pA[0] + 0.587f*pA[H*W] + 0.114f*pA[2*H*W];
        float lB = 0.2989f*pB[0] + 0.587f*pB[H*W] + 0.114f*pB[2*H*W];
        float wc = hann512(col);
        r[j] = make_float2(lA * wrA * wc, lB * wrB * wc);
    }

    fft512(r, s_re[f], s_im[f], tl);

    // store full spectrum (natural order) into this slot's buffer
    __syncthreads();
    {
        int k0 = tl >> 3, k1 = tl & 7;
        #pragma unroll
        for (int k2 = 0; k2 < 8; k2++) {
            int k = k0 + 8*k1 + 64*k2;
            s_re[f][k] = r[k2].x;
            s_im[f][k] = r[k2].y;
        }
    }
    __syncthreads();

    // block-wide unpack + coalesced transposed write (8 consecutive rows per k)
    const int j    = tid & 7;    // row within group of 8
    const int kidx = tid >> 3;   // 0..31
    const int fp   = j >> 1;     // source FFT slot
    const int isB  = j & 1;
    const float* zr = s_re[fp];
    const float* zi = s_im[fp];
    float2* dst = d_scratch + (size_t)img * KCOLS * H + rg * 8 + j;

    #pragma unroll
    for (int q = 0; q < 9; q++) {
        int k = kidx + 32 * q;
        if (k > 256) break;
        int km = (512 - k) & 511;
        float ax = zr[k],  ay = zi[k];
        float bx = zr[km], by = -zi[km];     // conj(Z[N-k])
        float2 o;
        if (!isB) o = make_float2(0.5f*(ax + bx),  0.5f*(ay + by));
        else      o = make_float2(0.5f*(ay - by), -0.5f*(ax - bx));
        dst[(size_t)k * H] = o;
    }
}

// ---------------- column pass: FFT + log-magnitude + binning (with mirror) ----
// grid (65, 32), block 256: 4 FFT slots, kcol = bx*4 + f (valid <= 256)
__global__ void __launch_bounds__(256) k_colfft() {
    __shared__ float s_re[4][SBUF];
    __shared__ float s_im[4][SBUF];
    __shared__ float s_bins[8][NBINS];

    const int tid = threadIdx.x;
    const int f  = tid >> 6;
    const int tl = tid & 63;
    const int img  = blockIdx.y;
    const int kcol = blockIdx.x * 4 + f;
    const int kload = (kcol <= 256) ? kcol : 256;

    for (int i = tid; i < 8 * NBINS; i += 256) ((float*)s_bins)[i] = 0.0f;

    const float2* src = d_scratch + (size_t)img * KCOLS * H + (size_t)kload * H;
    float2 r[8];
    #pragma unroll
    for (int j = 0; j < 8; j++) r[j] = src[tl + 64 * j];

    fft512(r, s_re[f], s_im[f], tl);

    // magnitudes + bin accumulation
    if (kcol <= 256) {
        const int warp = tid >> 5;
        const int k0 = tl >> 3, k1 = tl & 7;
        const bool mirror = (kcol >= 1 && kcol <= 255);
        const unsigned char* bm  = d_binmapT + (size_t)kcol * H;
        const unsigned char* bmm = d_binmapT + (size_t)(512 - kcol) * H;  // only used if mirror
        #pragma unroll
        for (int k2 = 0; k2 < 8; k2++) {
            int k = k0 + 8*k1 + 64*k2;
            float2 fv = r[k2];
            float mag = log1pf(sqrtf(fv.x*fv.x + fv.y*fv.y));
            unsigned char b1 = bm[k];
            if (b1 < NBINS) atomicAdd(&s_bins[warp][b1], mag);
            if (mirror) {
                unsigned char b2 = bmm[(512 - k) & 511];
                if (b2 < NBINS) atomicAdd(&s_bins[warp][b2], mag);
            }
        }
    }
    __syncthreads();
    if (tid < NBINS) {
        float s = 0.0f;
        #pragma unroll
        for (int w = 0; w < 8; w++) s += s_bins[w][tid];
        atomicAdd(&d_sums[img * NBINS + tid], s);
    }
}

// ---------------- finalize ----------------
__global__ void k_final(const float* __restrict__ rw, float* __restrict__ out) {
    const int t = threadIdx.x;  // 768 threads
    __shared__ float e[NIMG * NBINS];
    __shared__ float denom[NIMG * 3];
    __shared__ float red[NIMG * NBINS];

    {
        float c = (float)d_counts[t % NBINS];
        e[t] = d_sums[t] / fmaxf(c, 1e-6f);
    }
    __syncthreads();

    if (t < NIMG * 3) {
        int img = t / 3, rr = t % 3;
        float s = 0.0f;
        #pragma unroll
        for (int a = 0; a < 8; a++) s += e[img * NBINS + rr * 8 + a];
        denom[t] = fmaxf(s, 1e-6f);
    }
    __syncthreads();

    float term = 0.0f;
    if (t < 16 * NBINS) {
        int b = t / NBINS, rest = t % NBINS, rr = rest / 8;
        float pe = e[b * NBINS + rest]        / denom[b * 3 + rr];
        float te = e[(16 + b) * NBINS + rest] / denom[(16 + b) * 3 + rr];
        float d = pe - te;
        term = sqrtf(d * d + 1e-6f) * rw[rr];
    }
    red[t] = term;
    __syncthreads();

    for (int off = 384; off > 2; off >>= 1) {
        if (t < off) red[t] += red[t + off];
        __syncthreads();
    }
    if (t == 0) out[0] = (red[0] + red[1] + red[2]) / 384.0f;
}

// ---------------- launcher ----------------
extern "C" void kernel_launch(void* const* d_in, const int* in_sizes, int n_in,
                              void* d_out, int out_size) {
    const float* pred = (const float*)d_in[0];
    const float* tgt  = (const float*)d_in[1];
    const float* rw   = (const float*)d_in[2];
    float* out = (float*)d_out;

    k_init<<<1, 1024>>>();
    k_binmap<<<W, H>>>();
    k_rowfft<<<dim3(64, NIMG), 256>>>(pred, tgt);
    k_colfft<<<dim3(65, NIMG), 256>>>();
    k_final<<<1, NIMG * NBINS>>>(rw, out);
}

// round 3
// speedup vs baseline: 4.7042x; 1.4342x over previous
#include <cuda_runtime.h>
#include <math.h>

#define PI_F 3.14159274101257324f   // float32(pi)
#define H 512
#define W 512
#define NIMG 32                      // 16 pred + 16 tgt
#define NBINS 24                     // 3 radial * 8 angle
#define KCOLS 257                    // Hermitian: only cols 0..256 stored

// ---- scratch (static device globals; no allocations allowed) ----
__device__ float2 d_scratch[(size_t)NIMG * KCOLS * H];   // [img][kcol][row], 33.7 MB
__device__ float  d_sums[NIMG * NBINS];
__device__ int    d_counts[NBINS];
__device__ unsigned char d_binmapT[W * H];               // [v][u], transposed bin map

// float32 linspace(-1, 1, 512) as numpy/jax computes it: i*step + start
__device__ __forceinline__ float lin512(int i) {
    const float step = 2.0f / 511.0f;
    return (float)i * step + (-1.0f);
}
__device__ __forceinline__ float hann512(int n) {
    return 0.5f * (1.0f - cosf((6.283185307179586f * (float)n) / 511.0f));
}

// ---------------- complex helpers ----------------
__device__ __forceinline__ float2 cadd(float2 a, float2 b){return make_float2(a.x+b.x,a.y+b.y);}
__device__ __forceinline__ float2 csub(float2 a, float2 b){return make_float2(a.x-b.x,a.y-b.y);}
__device__ __forceinline__ float2 cmul(float2 a, float2 b){return make_float2(a.x*b.x-a.y*b.y, a.x*b.y+a.y*b.x);}
__device__ __forceinline__ float2 mulmj(float2 a){return make_float2(a.y,-a.x);} // * (-i)

// 8-point DFT in registers (DIF, result reordered to natural frequency order)
__device__ __forceinline__ void fft8(float2 r[8]) {
    const float C = 0.70710678118654752f;
    float2 u0=cadd(r[0],r[4]), u4=csub(r[0],r[4]);
    float2 u1=cadd(r[1],r[5]), u5=csub(r[1],r[5]);
    float2 u2=cadd(r[2],r[6]), u6=csub(r[2],r[6]);
    float2 u3=cadd(r[3],r[7]), u7=csub(r[3],r[7]);
    u5 = make_float2(C*(u5.x+u5.y), C*(u5.y-u5.x));      // * W8^1
    u6 = mulmj(u6);                                      // * W8^2
    u7 = make_float2(C*(u7.y-u7.x), -C*(u7.x+u7.y));     // * W8^3
    float2 v0=cadd(u0,u2), v2=csub(u0,u2);
    float2 v1=cadd(u1,u3), v3=mulmj(csub(u1,u3));
    float2 v4=cadd(u4,u6), v6=csub(u4,u6);
    float2 v5=cadd(u5,u7), v7=mulmj(csub(u5,u7));
    r[0]=cadd(v0,v1); r[4]=csub(v0,v1);
    r[2]=cadd(v2,v3); r[6]=csub(v2,v3);
    r[1]=cadd(v4,v5); r[5]=csub(v4,v5);
    r[3]=cadd(v6,v7); r[7]=csub(v6,v7);
}

#define PAD1 72   // exchange-1 row stride (floats): conflict-free
#define PAD2 72   // exchange-2 k0 stride (floats)
#define SBUF 584  // per-slot buffer size (floats)

// 512-pt FFT: 64 threads (tl), 8 values/thread. Input r[j] = x[tl + 64*j].
// Output: r[k2] = X[k0 + 8*k1 + 64*k2] with k0 = tl>>3, k1 = tl&7.
// Uses block-wide __syncthreads (all slots in block must call together).
__device__ __forceinline__ void fft512(float2 r[8], float* sre, float* sim, int tl) {
    // stage 1: DFT over j -> k0, twiddle W512^{tl*k0}
    fft8(r);
    float s, c;
    __sincosf(-6.283185307179586f * (float)tl / 512.0f, &s, &c);
    float2 w = make_float2(c, s), wk = w;
    #pragma unroll
    for (int k = 1; k < 8; k++) { r[k] = cmul(r[k], wk); wk = cmul(wk, w); }
    // exchange 1: sh[k0*PAD1 + m], m = tl   (bank: 8k + tl -> clean)
    #pragma unroll
    for (int k = 0; k < 8; k++) { sre[k*PAD1 + tl] = r[k].x; sim[k*PAD1 + tl] = r[k].y; }
    __syncthreads();
    int k0 = tl >> 3, m0 = tl & 7;
    #pragma unroll
    for (int m1 = 0; m1 < 8; m1++) {
        int a = k0*PAD1 + m0 + 8*m1;           // bank: 8k0 + m0 -> clean
        r[m1] = make_float2(sre[a], sim[a]);
    }
    // stage 2: DFT over m1 -> k1, twiddle W64^{m0*k1}
    fft8(r);
    __sincosf(-6.283185307179586f * (float)m0 / 64.0f, &s, &c);
    w = make_float2(c, s); wk = w;
    #pragma unroll
    for (int k = 1; k < 8; k++) { r[k] = cmul(r[k], wk); wk = cmul(wk, w); }
    __syncthreads();
    // exchange 2: sh[k0*PAD2 + 9*m0 + k]  (bank: 8k0 + 9m0 + k -> clean)
    #pragma unroll
    for (int k = 0; k < 8; k++) { sre[k0*PAD2 + 9*m0 + k] = r[k].x; sim[k0*PAD2 + 9*m0 + k] = r[k].y; }
    __syncthreads();
    int k1 = tl & 7;
    #pragma unroll
    for (int m = 0; m < 8; m++) {
        int a = k0*PAD2 + 9*m + k1;            // bank: 8k0 + k1 + 9m -> clean
        r[m] = make_float2(sre[a], sim[a]);
    }
    // stage 3: DFT over m0 -> k2 (no twiddle)
    fft8(r);
}

// ---------------- init ----------------
__global__ void k_init() {
    int t = threadIdx.x;
    if (t < NIMG * NBINS) d_sums[t] = 0.0f;
    if (t < NBINS) d_counts[t] = 0;
}

// ---------------- polar bin map (transposed) + counts ----------------
__global__ void k_binmap() {
    int v = blockIdx.x;    // unshifted freq col
    int u = threadIdx.x;   // unshifted freq row
    __shared__ int cnt[NBINS];
    if (u < NBINS) cnt[u] = 0;
    __syncthreads();

    int i = (u + H/2) & (H - 1);
    int j = (v + W/2) & (W - 1);
    float yv = lin512(i);
    float xv = lin512(j);

    float rad = sqrtf(xv*xv + yv*yv) / sqrtf(2.0f);
    float a = atan2f(yv, xv);
    a = fmodf(a, PI_F);
    if (a < 0.0f) a += PI_F;

    const float rstep = (0.9f - 0.08f) / 3.0f;
    float re1 = 1.0f * rstep + 0.08f;
    float re2 = 2.0f * rstep + 0.08f;
    int rb = -1;
    if (rad >= 0.08f && rad < re1) rb = 0;
    else if (rad >= re1 && rad < re2) rb = 1;
    else if (rad >= re2 && rad <= 0.9f) rb = 2;

    const float astep = PI_F / 8.0f;
    int ab = 7;
    #pragma unroll
    for (int k = 0; k < 7; k++) {
        float e0 = (float)k * astep;
        float e1 = (float)(k+1) * astep;
        if (a >= e0 && a < e1) { ab = k; break; }
    }

    unsigned char bin = 255;
    if (rb >= 0) bin = (unsigned char)(rb * 8 + ab);
    d_binmapT[v * H + u] = bin;

    if (bin < NBINS) atomicAdd(&cnt[bin], 1);
    __syncthreads();
    if (u < NBINS && cnt[u] > 0) atomicAdd(&d_counts[u], cnt[u]);
}

// ---------------- row pass: 2 real rows per complex FFT, unpack, transposed write ----
// grid (64, 32), block 256: 4 FFT slots, slot f handles rows rg*8+2f, rg*8+2f+1
__global__ void __launch_bounds__(256) k_rowfft(const float* __restrict__ pred,
                                                const float* __restrict__ tgt) {
    __shared__ float s_re[4][SBUF];
    __shared__ float s_im[4][SBUF];

    const int tid = threadIdx.x;
    const int f  = tid >> 6;
    const int tl = tid & 63;
    const int rg  = blockIdx.x;   // row group (8 rows)
    const int img = blockIdx.y;

    const float* base = (img < 16)
        ? pred + (size_t)img * 3 * H * W
        : tgt  + (size_t)(img - 16) * 3 * H * W;

    const int rA = rg * 8 + 2 * f;
    const int rB = rA + 1;
    const float wrA = hann512(rA);
    const float wrB = hann512(rB);

    float2 r[8];
    #pragma unroll
    for (int j = 0; j < 8; j++) {
        int col = tl + 64 * j;
        const float* pA = base + (size_t)rA * W + col;
        const float* pB = base + (size_t)rB * W + col;
        float lA = 0.2989f*pA[0] + 0.587f*pA[H*W] + 0.114f*pA[2*H*W];
        float lB = 0.2989f*pB[0] + 0.587f*pB[H*W] + 0.114f*pB[2*H*W];
        float wc = hann512(col);
        r[j] = make_float2(lA * wrA * wc, lB * wrB * wc);
    }

    fft512(r, s_re[f], s_im[f], tl);

    // store full spectrum (natural order) into this slot's buffer
    __syncthreads();
    {
        int k0 = tl >> 3, k1 = tl & 7;
        #pragma unroll
        for (int k2 = 0; k2 < 8; k2++) {
            int k = k0 + 8*k1 + 64*k2;
            s_re[f][k] = r[k2].x;
            s_im[f][k] = r[k2].y;
        }
    }
    __syncthreads();

    // block-wide unpack + coalesced transposed write (8 consecutive rows per k)
    const int j    = tid & 7;    // row within group of 8
    const int kidx = tid >> 3;   // 0..31
    const int fp   = j >> 1;     // source FFT slot
    const int isB  = j & 1;
    const float* zr = s_re[fp];
    const float* zi = s_im[fp];
    float2* dst = d_scratch + (size_t)img * KCOLS * H + rg * 8 + j;

    #pragma unroll
    for (int q = 0; q < 9; q++) {
        int k = kidx + 32 * q;
        if (k > 256) break;
        int km = (512 - k) & 511;
        float ax = zr[k],  ay = zi[k];
        float bx = zr[km], by = -zi[km];     // conj(Z[N-k])
        float2 o;
        if (!isB) o = make_float2(0.5f*(ax + bx),  0.5f*(ay + by));
        else      o = make_float2(0.5f*(ay - by), -0.5f*(ax - bx));
        dst[(size_t)k * H] = o;
    }
}

// ---------------- column pass: FFT + log-magnitude + binning (with mirror) ----
// grid (65, 32), block 256: 4 FFT slots, kcol = bx*4 + f (valid <= 256)
__global__ void __launch_bounds__(256) k_colfft() {
    __shared__ float s_re[4][SBUF];
    __shared__ float s_im[4][SBUF];
    __shared__ float s_bins[8][NBINS];

    const int tid = threadIdx.x;
    const int f  = tid >> 6;
    const int tl = tid & 63;
    const int img  = blockIdx.y;
    const int kcol = blockIdx.x * 4 + f;
    const int kload = (kcol <= 256) ? kcol : 256;

    for (int i = tid; i < 8 * NBINS; i += 256) ((float*)s_bins)[i] = 0.0f;

    const float2* src = d_scratch + (size_t)img * KCOLS * H + (size_t)kload * H;
    float2 r[8];
    #pragma unroll
    for (int j = 0; j < 8; j++) r[j] = src[tl + 64 * j];

    fft512(r, s_re[f], s_im[f], tl);

    // magnitudes + bin accumulation
    if (kcol <= 256) {
        const int warp = tid >> 5;
        const int k0 = tl >> 3, k1 = tl & 7;
        const bool mirror = (kcol >= 1 && kcol <= 255);
        const unsigned char* bm  = d_binmapT + (size_t)kcol * H;
        const unsigned char* bmm = d_binmapT + (size_t)(512 - kcol) * H;  // only used if mirror
        #pragma unroll
        for (int k2 = 0; k2 < 8; k2++) {
            int k = k0 + 8*k1 + 64*k2;
            float2 fv = r[k2];
            // fast log-magnitude: absolute error ~1e-7, far inside tolerance
            float mag = __logf(1.0f + __fsqrt_rn(fv.x*fv.x + fv.y*fv.y));
            unsigned char b1 = bm[k];
            if (mirror) {
                unsigned char b2 = bmm[(512 - k) & 511];
                if (b1 == b2) {
                    if (b1 < NBINS) atomicAdd(&s_bins[warp][b1], 2.0f * mag);
                } else {
                    if (b1 < NBINS) atomicAdd(&s_bins[warp][b1], mag);
                    if (b2 < NBINS) atomicAdd(&s_bins[warp][b2], mag);
                }
            } else {
                if (b1 < NBINS) atomicAdd(&s_bins[warp][b1], mag);
            }
        }
    }
    __syncthreads();
    if (tid < NBINS) {
        float s = 0.0f;
        #pragma unroll
        for (int w = 0; w < 8; w++) s += s_bins[w][tid];
        atomicAdd(&d_sums[img * NBINS + tid], s);
    }
}

// ---------------- finalize ----------------
__global__ void k_final(const float* __restrict__ rw, float* __restrict__ out) {
    const int t = threadIdx.x;  // 768 threads
    __shared__ float e[NIMG * NBINS];
    __shared__ float denom[NIMG * 3];
    __shared__ float red[NIMG * NBINS];

    {
        float c = (float)d_counts[t % NBINS];
        e[t] = d_sums[t] / fmaxf(c, 1e-6f);
    }
    __syncthreads();

    if (t < NIMG * 3) {
        int img = t / 3, rr = t % 3;
        float s = 0.0f;
        #pragma unroll
        for (int a = 0; a < 8; a++) s += e[img * NBINS + rr * 8 + a];
        denom[t] = fmaxf(s, 1e-6f);
    }
    __syncthreads();

    float term = 0.0f;
    if (t < 16 * NBINS) {
        int b = t / NBINS, rest = t % NBINS, rr = rest / 8;
        float pe = e[b * NBINS + rest]        / denom[b * 3 + rr];
        float te = e[(16 + b) * NBINS + rest] / denom[(16 + b) * 3 + rr];
        float d = pe - te;
        term = sqrtf(d * d + 1e-6f) * rw[rr];
    }
    red[t] = term;
    __syncthreads();

    for (int off = 384; off > 2; off >>= 1) {
        if (t < off) red[t] += red[t + off];
        __syncthreads();
    }
    if (t == 0) out[0] = (red[0] + red[1] + red[2]) / 384.0f;
}

// ---------------- launcher ----------------
extern "C" void kernel_launch(void* const* d_in, const int* in_sizes, int n_in,
                              void* d_out, int out_size) {
    const float* pred = (const float*)d_in[0];
    const float* tgt  = (const float*)d_in[1];
    const float* rw   = (const float*)d_in[2];
    float* out = (float*)d_out;

    k_init<<<1, 1024>>>();
    k_binmap<<<W, H>>>();
    k_rowfft<<<dim3(64, NIMG), 256>>>(pred, tgt);
    k_colfft<<<dim3(65, NIMG), 256>>>();
    k_final<<<1, NIMG * NBINS>>>(rw, out);
}

// round 4
// speedup vs baseline: 4.9577x; 1.0539x over previous
#include <cuda_runtime.h>
#include <math.h>

#define PI_F 3.14159274101257324f   // float32(pi)
#define H 512
#define W 512
#define NIMG 32                      // 16 pred + 16 tgt
#define NBINS 24                     // 3 radial * 8 angle
#define KCOLS 257                    // Hermitian: only cols 0..256 stored

// ---- scratch (static device globals; no allocations allowed) ----
__device__ float2 d_scratch[(size_t)NIMG * KCOLS * H];   // [img][kcol][row], 33.7 MB
__device__ float  d_sums[NIMG * NBINS];
__device__ int    d_counts[NBINS];
__device__ uchar2 d_binpair[KCOLS * H];   // per (kcol,row): encoded bin + mirror bin

// float32 linspace(-1, 1, 512) as numpy/jax computes it: i*step + start
__device__ __forceinline__ float lin512(int i) {
    const float step = 2.0f / 511.0f;
    return (float)i * step + (-1.0f);
}
__device__ __forceinline__ float hann512(int n) {
    return 0.5f * (1.0f - cosf((6.283185307179586f * (float)n) / 511.0f));
}

// ---------------- packed f32x2 helpers ----------------
__device__ __forceinline__ float2 f2add(float2 a, float2 b) {
    unsigned long long au = *(unsigned long long*)&a;
    unsigned long long bu = *(unsigned long long*)&b;
    unsigned long long ru;
    asm("add.rn.f32x2 %0, %1, %2;" : "=l"(ru) : "l"(au), "l"(bu));
    return *(float2*)&ru;
}
__device__ __forceinline__ float2 f2sub(float2 a, float2 b) {
    // a - b = fma(b, -1, a)
    unsigned long long au = *(unsigned long long*)&a;
    unsigned long long bu = *(unsigned long long*)&b;
    const float2 n1 = make_float2(-1.0f, -1.0f);
    unsigned long long nu = *(unsigned long long*)&n1;
    unsigned long long ru;
    asm("fma.rn.f32x2 %0, %1, %2, %3;" : "=l"(ru) : "l"(bu), "l"(nu), "l"(au));
    return *(float2*)&ru;
}
__device__ __forceinline__ float2 f2mul(float2 a, float2 b) {
    unsigned long long au = *(unsigned long long*)&a;
    unsigned long long bu = *(unsigned long long*)&b;
    unsigned long long ru;
    asm("mul.rn.f32x2 %0, %1, %2;" : "=l"(ru) : "l"(au), "l"(bu));
    return *(float2*)&ru;
}

// ---------------- complex helpers ----------------
__device__ __forceinline__ float2 cmul(float2 a, float2 b){return make_float2(a.x*b.x-a.y*b.y, a.x*b.y+a.y*b.x);}
__device__ __forceinline__ float2 mulmj(float2 a){return make_float2(a.y,-a.x);} // * (-i)

// 8-point DFT in registers (DIF, result reordered to natural frequency order)
__device__ __forceinline__ void fft8(float2 r[8]) {
    const float Cc = 0.70710678118654752f;
    const float2 C2 = make_float2(Cc, Cc);
    float2 u0=f2add(r[0],r[4]), u4=f2sub(r[0],r[4]);
    float2 u1=f2add(r[1],r[5]), u5=f2sub(r[1],r[5]);
    float2 u2=f2add(r[2],r[6]), u6=f2sub(r[2],r[6]);
    float2 u3=f2add(r[3],r[7]), u7=f2sub(r[3],r[7]);
    // u5 *= W8^1 = C*(1 - i):  (x,y) -> (C*(x+y), C*(y-x))
    float2 t5 = f2add(u5, mulmj(u5));      // (x+y, y-x)
    u5 = f2mul(t5, C2);
    u6 = mulmj(u6);                        // * W8^2 = -i
    // u7 *= W8^3 = C*(-1 - i): (x,y) -> (C*(y-x), -C*(x+y))
    float2 t7 = f2add(u7, mulmj(u7));      // (x+y, y-x)
    u7 = f2mul(mulmj(t7), C2);             // (y-x, -(x+y)) * C
    float2 v0=f2add(u0,u2), v2=f2sub(u0,u2);
    float2 v1=f2add(u1,u3), v3=mulmj(f2sub(u1,u3));
    float2 v4=f2add(u4,u6), v6=f2sub(u4,u6);
    float2 v5=f2add(u5,u7), v7=mulmj(f2sub(u5,u7));
    r[0]=f2add(v0,v1); r[4]=f2sub(v0,v1);
    r[2]=f2add(v2,v3); r[6]=f2sub(v2,v3);
    r[1]=f2add(v4,v5); r[5]=f2sub(v4,v5);
    r[3]=f2add(v6,v7); r[7]=f2sub(v6,v7);
}

#define PAD1 72   // exchange-1 row stride (floats): conflict-free
#define PAD2 72   // exchange-2 k0 stride (floats)
#define SBUF 584  // per-slot buffer size (floats)

// 512-pt FFT: 64 threads (tl), 8 values/thread. Input r[j] = x[tl + 64*j].
// Output: r[k2] = X[k0 + 8*k1 + 64*k2] with k0 = tl>>3, k1 = tl&7.
__device__ __forceinline__ void fft512(float2 r[8], float* sre, float* sim, int tl) {
    // stage 1: DFT over j -> k0, twiddle W512^{tl*k0}
    fft8(r);
    float s, c;
    __sincosf(-6.283185307179586f * (float)tl / 512.0f, &s, &c);
    float2 w = make_float2(c, s), wk = w;
    #pragma unroll
    for (int k = 1; k < 8; k++) { r[k] = cmul(r[k], wk); wk = cmul(wk, w); }
    // exchange 1: sh[k0*PAD1 + m], m = tl   (bank: 8k + tl -> clean)
    #pragma unroll
    for (int k = 0; k < 8; k++) { sre[k*PAD1 + tl] = r[k].x; sim[k*PAD1 + tl] = r[k].y; }
    __syncthreads();
    int k0 = tl >> 3, m0 = tl & 7;
    #pragma unroll
    for (int m1 = 0; m1 < 8; m1++) {
        int a = k0*PAD1 + m0 + 8*m1;           // bank: 8k0 + m0 -> clean
        r[m1] = make_float2(sre[a], sim[a]);
    }
    // stage 2: DFT over m1 -> k1, twiddle W64^{m0*k1}
    fft8(r);
    __sincosf(-6.283185307179586f * (float)m0 / 64.0f, &s, &c);
    w = make_float2(c, s); wk = w;
    #pragma unroll
    for (int k = 1; k < 8; k++) { r[k] = cmul(r[k], wk); wk = cmul(wk, w); }
    __syncthreads();
    // exchange 2: sh[k0*PAD2 + 9*m0 + k]  (bank: 8k0 + 9m0 + k -> clean)
    #pragma unroll
    for (int k = 0; k < 8; k++) { sre[k0*PAD2 + 9*m0 + k] = r[k].x; sim[k0*PAD2 + 9*m0 + k] = r[k].y; }
    __syncthreads();
    int k1 = tl & 7;
    #pragma unroll
    for (int m = 0; m < 8; m++) {
        int a = k0*PAD2 + 9*m + k1;            // bank: 8k0 + k1 + 9m -> clean
        r[m] = make_float2(sre[a], sim[a]);
    }
    // stage 3: DFT over m0 -> k2 (no twiddle)
    fft8(r);
}

// ---------------- init ----------------
__global__ void k_init() {
    int t = threadIdx.x;
    if (t < NIMG * NBINS) d_sums[t] = 0.0f;
    if (t < NBINS) d_counts[t] = 0;
}

// ---------------- bin of one (u=row, v=col) unshifted freq point ----------------
__device__ __forceinline__ int binof(int u, int v) {
    int i = (u + H/2) & (H - 1);
    int j = (v + W/2) & (W - 1);
    float yv = lin512(i);
    float xv = lin512(j);

    float rad = sqrtf(xv*xv + yv*yv) / sqrtf(2.0f);
    float a = atan2f(yv, xv);
    a = fmodf(a, PI_F);
    if (a < 0.0f) a += PI_F;

    const float rstep = (0.9f - 0.08f) / 3.0f;
    float re1 = 1.0f * rstep + 0.08f;
    float re2 = 2.0f * rstep + 0.08f;
    int rb = -1;
    if (rad >= 0.08f && rad < re1) rb = 0;
    else if (rad >= re1 && rad < re2) rb = 1;
    else if (rad >= re2 && rad <= 0.9f) rb = 2;

    const float astep = PI_F / 8.0f;
    int ab = 7;
    #pragma unroll
    for (int k = 0; k < 7; k++) {
        float e0 = (float)k * astep;
        float e1 = (float)(k+1) * astep;
        if (a >= e0 && a < e1) { ab = k; break; }
    }
    return (rb >= 0) ? (rb * 8 + ab) : 255;
}

// ---------------- bin-pair map + counts: grid 257, block 512 ----------------
// e1: bits0-4 bin (31=none), bit6 = double-weight; e2: second bin (255=none)
__global__ void k_binpair() {
    int kcol = blockIdx.x;     // 0..256
    int k = threadIdx.x;       // row 0..511
    __shared__ int cnt[NBINS];
    if (k < NBINS) cnt[k] = 0;
    __syncthreads();

    int b1 = binof(k, kcol);
    bool hasm = (kcol >= 1 && kcol <= 255);
    int b2 = hasm ? binof((512 - k) & 511, 512 - kcol) : 255;

    unsigned char e1 = 31, e2 = 255;
    if (b1 < NBINS && b2 == b1) {
        e1 = (unsigned char)(b1 | 64);
        atomicAdd(&cnt[b1], 2);
    } else {
        if (b1 < NBINS) { e1 = (unsigned char)b1; atomicAdd(&cnt[b1], 1); }
        if (b2 < NBINS) { e2 = (unsigned char)b2; atomicAdd(&cnt[b2], 1); }
    }
    d_binpair[kcol * H + k] = make_uchar2(e1, e2);

    __syncthreads();
    if (k < NBINS && cnt[k] > 0) atomicAdd(&d_counts[k], cnt[k]);
}

// ---------------- row pass: 2 real rows per complex FFT, unpack, transposed write ----
__global__ void __launch_bounds__(256) k_rowfft(const float* __restrict__ pred,
                                                const float* __restrict__ tgt) {
    __shared__ float s_re[4][SBUF];
    __shared__ float s_im[4][SBUF];

    const int tid = threadIdx.x;
    const int f  = tid >> 6;
    const int tl = tid & 63;
    const int rg  = blockIdx.x;   // row group (8 rows)
    const int img = blockIdx.y;

    const float* base = (img < 16)
        ? pred + (size_t)img * 3 * H * W
        : tgt  + (size_t)(img - 16) * 3 * H * W;

    const int rA = rg * 8 + 2 * f;
    const int rB = rA + 1;
    const float wrA = hann512(rA);
    const float wrB = hann512(rB);

    float2 r[8];
    #pragma unroll
    for (int j = 0; j < 8; j++) {
        int col = tl + 64 * j;
        const float* pA = base + (size_t)rA * W + col;
        const float* pB = base + (size_t)rB * W + col;
        float lA = 0.2989f*pA[0] + 0.587f*pA[H*W] + 0.114f*pA[2*H*W];
        float lB = 0.2989f*pB[0] + 0.587f*pB[H*W] + 0.114f*pB[2*H*W];
        float wc = hann512(col);
        r[j] = make_float2(lA * wrA * wc, lB * wrB * wc);
    }

    fft512(r, s_re[f], s_im[f], tl);

    // store full spectrum (natural order) into this slot's buffer
    __syncthreads();
    {
        int k0 = tl >> 3, k1 = tl & 7;
        #pragma unroll
        for (int k2 = 0; k2 < 8; k2++) {
            int k = k0 + 8*k1 + 64*k2;
            s_re[f][k] = r[k2].x;
            s_im[f][k] = r[k2].y;
        }
    }
    __syncthreads();

    // block-wide unpack + coalesced transposed write (8 consecutive rows per k)
    const int j    = tid & 7;    // row within group of 8
    const int kidx = tid >> 3;   // 0..31
    const int fp   = j >> 1;     // source FFT slot
    const int isB  = j & 1;
    const float* zr = s_re[fp];
    const float* zi = s_im[fp];
    float2* dst = d_scratch + (size_t)img * KCOLS * H + rg * 8 + j;

    #pragma unroll
    for (int q = 0; q < 9; q++) {
        int k = kidx + 32 * q;
        if (k > 256) break;
        int km = (512 - k) & 511;
        float ax = zr[k],  ay = zi[k];
        float bx = zr[km], by = -zi[km];     // conj(Z[N-k])
        float2 o;
        if (!isB) o = make_float2(0.5f*(ax + bx),  0.5f*(ay + by));
        else      o = make_float2(0.5f*(ay - by), -0.5f*(ax - bx));
        dst[(size_t)k * H] = o;
    }
}

// ---------------- column pass: FFT + log-magnitude + binning ----
// grid (65, 32), block 256: 4 FFT slots, kcol = bx*4 + f (valid <= 256)
__global__ void __launch_bounds__(256, 7) k_colfft() {
    __shared__ float s_re[4][SBUF];
    __shared__ float s_im[4][SBUF];
    __shared__ float s_bins[8][NBINS];

    const int tid = threadIdx.x;
    const int f  = tid >> 6;
    const int tl = tid & 63;
    const int img  = blockIdx.y;
    const int kcol = blockIdx.x * 4 + f;
    const int kload = (kcol <= 256) ? kcol : 256;

    for (int i = tid; i < 8 * NBINS; i += 256) ((float*)s_bins)[i] = 0.0f;

    const float2* src = d_scratch + (size_t)img * KCOLS * H + (size_t)kload * H;
    float2 r[8];
    #pragma unroll
    for (int j = 0; j < 8; j++) r[j] = src[tl + 64 * j];

    fft512(r, s_re[f], s_im[f], tl);

    // magnitudes + bin accumulation (mirror pre-merged in d_binpair)
    if (kcol <= 256) {
        const int warp = tid >> 5;
        const int k0 = tl >> 3, k1 = tl & 7;
        const uchar2* bp = d_binpair + (size_t)kcol * H;
        #pragma unroll
        for (int k2 = 0; k2 < 8; k2++) {
            int k = k0 + 8*k1 + 64*k2;
            float2 fv = r[k2];
            float mag = __logf(1.0f + __fsqrt_rn(fv.x*fv.x + fv.y*fv.y));
            uchar2 p = bp[k];
            unsigned b1 = p.x & 31u;
            if (b1 < NBINS) {
                float wm = (p.x & 64u) ? (mag + mag) : mag;
                atomicAdd(&s_bins[warp][b1], wm);
            }
            if (p.y < NBINS) atomicAdd(&s_bins[warp][p.y], mag);
        }
    }
    __syncthreads();
    if (tid < NBINS) {
        float s = 0.0f;
        #pragma unroll
        for (int w = 0; w < 8; w++) s += s_bins[w][tid];
        atomicAdd(&d_sums[img * NBINS + tid], s);
    }
}

// ---------------- finalize ----------------
__global__ void k_final(const float* __restrict__ rw, float* __restrict__ out) {
    const int t = threadIdx.x;  // 768 threads
    __shared__ float e[NIMG * NBINS];
    __shared__ float denom[NIMG * 3];
    __shared__ float red[NIMG * NBINS];

    {
        float c = (float)d_counts[t % NBINS];
        e[t] = d_sums[t] / fmaxf(c, 1e-6f);
    }
    __syncthreads();

    if (t < NIMG * 3) {
        int img = t / 3, rr = t % 3;
        float s = 0.0f;
        #pragma unroll
        for (int a = 0; a < 8; a++) s += e[img * NBINS + rr * 8 + a];
        denom[t] = fmaxf(s, 1e-6f);
    }
    __syncthreads();

    float term = 0.0f;
    if (t < 16 * NBINS) {
        int b = t / NBINS, rest = t % NBINS, rr = rest / 8;
        float pe = e[b * NBINS + rest]        / denom[b * 3 + rr];
        float te = e[(16 + b) * NBINS + rest] / denom[(16 + b) * 3 + rr];
        float d = pe - te;
        term = sqrtf(d * d + 1e-6f) * rw[rr];
    }
    red[t] = term;
    __syncthreads();

    for (int off = 384; off > 2; off >>= 1) {
        if (t < off) red[t] += red[t + off];
        __syncthreads();
    }
    if (t == 0) out[0] = (red[0] + red[1] + red[2]) / 384.0f;
}

// ---------------- launcher ----------------
extern "C" void kernel_launch(void* const* d_in, const int* in_sizes, int n_in,
                              void* d_out, int out_size) {
    const float* pred = (const float*)d_in[0];
    const float* tgt  = (const float*)d_in[1];
    const float* rw   = (const float*)d_in[2];
    float* out = (float*)d_out;

    k_init<<<1, 1024>>>();
    k_binpair<<<KCOLS, 512>>>();
    k_rowfft<<<dim3(64, NIMG), 256>>>(pred, tgt);
    k_colfft<<<dim3(65, NIMG), 256>>>();
    k_final<<<1, NIMG * NBINS>>>(rw, out);
}

// round 5
// speedup vs baseline: 7.5429x; 1.5214x over previous
#include <cuda_runtime.h>
#include <math.h>

#define PI_F 3.14159274101257324f   // float32(pi)
#define H 512
#define W 512
#define NIMG 32                      // 16 pred + 16 tgt
#define NBINS 24                     // 3 radial * 8 angle
#define KCOLS 257                    // Hermitian: only cols 0..256 stored

// ---- scratch (static device globals; no allocations allowed) ----
__device__ float2 d_scratch[(size_t)NIMG * KCOLS * H];   // [img][kcol][row], 33.7 MB
__device__ float  d_sums[NIMG * NBINS];
__device__ int    d_counts[NBINS];
__device__ __align__(16) uchar2 d_binpair[KCOLS * H];    // per (kcol,row): encoded bin + mirror bin

// float32 linspace(-1, 1, 512) as numpy/jax computes it: i*step + start
__device__ __forceinline__ float lin512(int i) {
    const float step = 2.0f / 511.0f;
    return (float)i * step + (-1.0f);
}
__device__ __forceinline__ float hann512(int n) {
    return 0.5f * (1.0f - cosf((6.283185307179586f * (float)n) / 511.0f));
}

// ---------------- packed f32x2 helpers ----------------
__device__ __forceinline__ float2 f2add(float2 a, float2 b) {
    unsigned long long au = *(unsigned long long*)&a;
    unsigned long long bu = *(unsigned long long*)&b;
    unsigned long long ru;
    asm("add.rn.f32x2 %0, %1, %2;" : "=l"(ru) : "l"(au), "l"(bu));
    return *(float2*)&ru;
}
__device__ __forceinline__ float2 f2sub(float2 a, float2 b) {
    unsigned long long au = *(unsigned long long*)&a;
    unsigned long long bu = *(unsigned long long*)&b;
    const float2 n1 = make_float2(-1.0f, -1.0f);
    unsigned long long nu = *(unsigned long long*)&n1;
    unsigned long long ru;
    asm("fma.rn.f32x2 %0, %1, %2, %3;" : "=l"(ru) : "l"(bu), "l"(nu), "l"(au));
    return *(float2*)&ru;
}
__device__ __forceinline__ float2 f2mul(float2 a, float2 b) {
    unsigned long long au = *(unsigned long long*)&a;
    unsigned long long bu = *(unsigned long long*)&b;
    unsigned long long ru;
    asm("mul.rn.f32x2 %0, %1, %2;" : "=l"(ru) : "l"(au), "l"(bu));
    return *(float2*)&ru;
}

// ---------------- complex helpers ----------------
__device__ __forceinline__ float2 cmul(float2 a, float2 b){return make_float2(a.x*b.x-a.y*b.y, a.x*b.y+a.y*b.x);}
__device__ __forceinline__ float2 mulmj(float2 a){return make_float2(a.y,-a.x);} // * (-i)

// 8-point DFT in registers (DIF, natural frequency order out)
__device__ __forceinline__ void fft8(float2 r[8]) {
    const float Cc = 0.70710678118654752f;
    const float2 C2 = make_float2(Cc, Cc);
    float2 u0=f2add(r[0],r[4]), u4=f2sub(r[0],r[4]);
    float2 u1=f2add(r[1],r[5]), u5=f2sub(r[1],r[5]);
    float2 u2=f2add(r[2],r[6]), u6=f2sub(r[2],r[6]);
    float2 u3=f2add(r[3],r[7]), u7=f2sub(r[3],r[7]);
    float2 t5 = f2add(u5, mulmj(u5));      // (x+y, y-x)
    u5 = f2mul(t5, C2);                    // * W8^1
    u6 = mulmj(u6);                        // * W8^2
    float2 t7 = f2add(u7, mulmj(u7));
    u7 = f2mul(mulmj(t7), C2);             // * W8^3
    float2 v0=f2add(u0,u2), v2=f2sub(u0,u2);
    float2 v1=f2add(u1,u3), v3=mulmj(f2sub(u1,u3));
    float2 v4=f2add(u4,u6), v6=f2sub(u4,u6);
    float2 v5=f2add(u5,u7), v7=mulmj(f2sub(u5,u7));
    r[0]=f2add(v0,v1); r[4]=f2sub(v0,v1);
    r[2]=f2add(v2,v3); r[6]=f2sub(v2,v3);
    r[1]=f2add(v4,v5); r[5]=f2sub(v4,v5);
    r[3]=f2add(v6,v7); r[7]=f2sub(v6,v7);
}

#define PADF 72    // float2 stride: 72 mod 16 == 8 -> conflict-free LDS.64/STS.64 both exchanges
#define SLOT 576   // float2 per slot (max idx 574)

// natural-order padded index (conflict-free for consecutive-row reads)
__device__ __forceinline__ int natidx(int k){ return 9*(k>>3) + (k&7); }

// 512-pt FFT: 64 threads (tl), 8 values/thread. Input r[j] = x[tl + 64*j].
// Output: r[k2] = X[k0 + 8*k1 + 64*k2] with k0 = tl>>3, k1 = tl&7.
__device__ __forceinline__ void fft512(float2 r[8], float2* sh, int tl) {
    fft8(r);
    float s, c;
    __sincosf(-6.283185307179586f * (float)tl / 512.0f, &s, &c);
    float2 w = make_float2(c, s), wk = w;
    #pragma unroll
    for (int k = 1; k < 8; k++) { r[k] = cmul(r[k], wk); wk = cmul(wk, w); }
    #pragma unroll
    for (int k = 0; k < 8; k++) sh[k*PADF + tl] = r[k];
    __syncthreads();
    int k0 = tl >> 3, m0 = tl & 7;
    #pragma unroll
    for (int m1 = 0; m1 < 8; m1++) r[m1] = sh[k0*PADF + m0 + 8*m1];
    fft8(r);
    __sincosf(-6.283185307179586f * (float)m0 / 64.0f, &s, &c);
    w = make_float2(c, s); wk = w;
    #pragma unroll
    for (int k = 1; k < 8; k++) { r[k] = cmul(r[k], wk); wk = cmul(wk, w); }
    __syncthreads();
    #pragma unroll
    for (int k = 0; k < 8; k++) sh[k0*PADF + 9*m0 + k] = r[k];
    __syncthreads();
    int k1 = tl & 7;
    #pragma unroll
    for (int m = 0; m < 8; m++) r[m] = sh[k0*PADF + 9*m + k1];
    fft8(r);
}

// ---------------- init ----------------
__global__ void k_init() {
    int t = threadIdx.x;
    if (t < NIMG * NBINS) d_sums[t] = 0.0f;
    if (t < NBINS) d_counts[t] = 0;
}

// ---------------- bin of one (u=row, v=col) unshifted freq point ----------------
__device__ __forceinline__ int binof(int u, int v) {
    int i = (u + H/2) & (H - 1);
    int j = (v + W/2) & (W - 1);
    float yv = lin512(i);
    float xv = lin512(j);

    float rad = sqrtf(xv*xv + yv*yv) / sqrtf(2.0f);
    float a = atan2f(yv, xv);
    a = fmodf(a, PI_F);
    if (a < 0.0f) a += PI_F;

    const float rstep = (0.9f - 0.08f) / 3.0f;
    float re1 = 1.0f * rstep + 0.08f;
    float re2 = 2.0f * rstep + 0.08f;
    int rb = -1;
    if (rad >= 0.08f && rad < re1) rb = 0;
    else if (rad >= re1 && rad < re2) rb = 1;
    else if (rad >= re2 && rad <= 0.9f) rb = 2;

    const float astep = PI_F / 8.0f;
    int ab = 7;
    #pragma unroll
    for (int k = 0; k < 7; k++) {
        float e0 = (float)k * astep;
        float e1 = (float)(k+1) * astep;
        if (a >= e0 && a < e1) { ab = k; break; }
    }
    return (rb >= 0) ? (rb * 8 + ab) : 255;
}

// ---------------- bin-pair map + counts: grid 257, block 512 ----------------
// e1: bits0-4 bin (31=none), bit6 = double-weight; e2: second bin (255=none)
__global__ void k_binpair() {
    int kcol = blockIdx.x;     // 0..256
    int k = threadIdx.x;       // row 0..511
    __shared__ int cnt[NBINS];
    if (k < NBINS) cnt[k] = 0;
    __syncthreads();

    int b1 = binof(k, kcol);
    bool hasm = (kcol >= 1 && kcol <= 255);
    int b2 = hasm ? binof((512 - k) & 511, 512 - kcol) : 255;

    unsigned char e1 = 31, e2 = 255;
    if (b1 < NBINS && b2 == b1) {
        e1 = (unsigned char)(b1 | 64);
        atomicAdd(&cnt[b1], 2);
    } else {
        if (b1 < NBINS) { e1 = (unsigned char)b1; atomicAdd(&cnt[b1], 1); }
        if (b2 < NBINS) { e2 = (unsigned char)b2; atomicAdd(&cnt[b2], 1); }
    }
    d_binpair[kcol * H + k] = make_uchar2(e1, e2);

    __syncthreads();
    if (k < NBINS && cnt[k] > 0) atomicAdd(&d_counts[k], cnt[k]);
}

// ---------------- row pass: 2 real rows per complex FFT, unpack, transposed write ----
__global__ void __launch_bounds__(256) k_rowfft(const float* __restrict__ pred,
                                                const float* __restrict__ tgt) {
    __shared__ float2 sh4[4][SLOT];

    const int tid = threadIdx.x;
    const int f  = tid >> 6;
    const int tl = tid & 63;
    const int rg  = blockIdx.x;   // row group (8 rows)
    const int img = blockIdx.y;

    const float* base = (img < 16)
        ? pred + (size_t)img * 3 * H * W
        : tgt  + (size_t)(img - 16) * 3 * H * W;

    const int rA = rg * 8 + 2 * f;
    const int rB = rA + 1;
    const float wrA = hann512(rA);
    const float wrB = hann512(rB);

    float2 r[8];
    #pragma unroll
    for (int j = 0; j < 8; j++) {
        int col = tl + 64 * j;
        const float* pA = base + (size_t)rA * W + col;
        const float* pB = base + (size_t)rB * W + col;
        float lA = 0.2989f*pA[0] + 0.587f*pA[H*W] + 0.114f*pA[2*H*W];
        float lB = 0.2989f*pB[0] + 0.587f*pB[H*W] + 0.114f*pB[2*H*W];
        float wc = hann512(col);
        r[j] = make_float2(lA * wrA * wc, lB * wrB * wc);
    }

    fft512(r, sh4[f], tl);

    // store spectrum in padded natural order
    __syncthreads();
    {
        int k0 = tl >> 3, k1 = tl & 7;
        #pragma unroll
        for (int k2 = 0; k2 < 8; k2++)
            sh4[f][natidx(k0 + 8*k1 + 64*k2)] = r[k2];
    }
    __syncthreads();

    // block-wide unpack + coalesced transposed write (8 consecutive rows per k)
    const int j    = tid & 7;    // row within group of 8
    const int kidx = tid >> 3;   // 0..31
    const int fp   = j >> 1;     // source FFT slot
    const int isB  = j & 1;
    const float2* z = sh4[fp];
    float2* dst = d_scratch + (size_t)img * KCOLS * H + rg * 8 + j;

    #pragma unroll
    for (int q = 0; q < 9; q++) {
        int k = kidx + 32 * q;
        if (k > 256) break;
        int km = (512 - k) & 511;
        float2 a = z[natidx(k)];
        float2 b = z[natidx(km)];
        float2 o;
        if (!isB) o = make_float2(0.5f*(a.x + b.x),  0.5f*(a.y - b.y));
        else      o = make_float2(0.5f*(a.y + b.y), -0.5f*(a.x - b.x));
        dst[(size_t)k * H] = o;
    }
}

// ---------------- column pass: FFT + log-magnitude + run-length binning ----
// grid (65, 32), block 256: 4 FFT slots, kcol = bx*4 + f (valid <= 256)
__global__ void __launch_bounds__(256, 7) k_colfft() {
    __shared__ float2 sh4[4][SLOT];
    __shared__ float s_bins[8][NBINS];

    const int tid = threadIdx.x;
    const int f  = tid >> 6;
    const int tl = tid & 63;
    const int img  = blockIdx.y;
    const int kcol = blockIdx.x * 4 + f;
    const int kload = (kcol <= 256) ? kcol : 256;

    for (int i = tid; i < 8 * NBINS; i += 256) ((float*)s_bins)[i] = 0.0f;

    const float2* src = d_scratch + (size_t)img * KCOLS * H + (size_t)kload * H;
    float2 r[8];
    #pragma unroll
    for (int j = 0; j < 8; j++) r[j] = src[tl + 64 * j];

    fft512(r, sh4[f], tl);

    // padded natural-order rewrite so each thread owns 8 consecutive rows
    __syncthreads();
    {
        int k0 = tl >> 3, k1 = tl & 7;
        #pragma unroll
        for (int k2 = 0; k2 < 8; k2++)
            sh4[f][natidx(k0 + 8*k1 + 64*k2)] = r[k2];
    }
    __syncthreads();

    if (kcol <= 256) {
        const int warp = tid >> 5;
        const float2* z = sh4[f] + 9 * tl;
        // 8 consecutive uchar2 bin-pairs = one 16B load
        uint4 pv = ((const uint4*)d_binpair)[kcol * 64 + tl];
        unsigned pw[4] = {pv.x, pv.y, pv.z, pv.w};

        int curb = 31;        // current run bin-code (31 = none)
        float acc = 0.0f;
        #pragma unroll
        for (int j = 0; j < 8; j++) {
            float2 fv = z[j];
            float mag = __logf(1.0f + __fsqrt_rn(fv.x*fv.x + fv.y*fv.y));
            unsigned half = pw[j >> 1] >> ((j & 1) * 16);
            unsigned e1 = half & 0xFFu;
            unsigned e2 = (half >> 8) & 0xFFu;
            unsigned b1 = e1 & 31u;
            float wm = (e1 & 64u) ? (mag + mag) : mag;
            if ((int)b1 != curb) {
                if (curb < NBINS) atomicAdd(&s_bins[warp][curb], acc);
                curb = (int)b1; acc = wm;
            } else {
                acc += wm;
            }
            if (e2 < NBINS) atomicAdd(&s_bins[warp][e2], mag);
        }
        if (curb < NBINS) atomicAdd(&s_bins[warp][curb], acc);
    }
    __syncthreads();
    if (tid < NBINS) {
        float s = 0.0f;
        #pragma unroll
        for (int w = 0; w < 8; w++) s += s_bins[w][tid];
        atomicAdd(&d_sums[img * NBINS + tid], s);
    }
}

// ---------------- finalize ----------------
__global__ void k_final(const float* __restrict__ rw, float* __restrict__ out) {
    const int t = threadIdx.x;  // 768 threads
    __shared__ float e[NIMG * NBINS];
    __shared__ float denom[NIMG * 3];
    __shared__ float red[NIMG * NBINS];

    {
        float c = (float)d_counts[t % NBINS];
        e[t] = d_sums[t] / fmaxf(c, 1e-6f);
    }
    __syncthreads();

    if (t < NIMG * 3) {
        int img = t / 3, rr = t % 3;
        float s = 0.0f;
        #pragma unroll
        for (int a = 0; a < 8; a++) s += e[img * NBINS + rr * 8 + a];
        denom[t] = fmaxf(s, 1e-6f);
    }
    __syncthreads();

    float term = 0.0f;
    if (t < 16 * NBINS) {
        int b = t / NBINS, rest = t % NBINS, rr = rest / 8;
        float pe = e[b * NBINS + rest]        / denom[b * 3 + rr];
        float te = e[(16 + b) * NBINS + rest] / denom[(16 + b) * 3 + rr];
        float d = pe - te;
        term = sqrtf(d * d + 1e-6f) * rw[rr];
    }
    red[t] = term;
    __syncthreads();

    for (int off = 384; off > 2; off >>= 1) {
        if (t < off) red[t] += red[t + off];
        __syncthreads();
    }
    if (t == 0) out[0] = (red[0] + red[1] + red[2]) / 384.0f;
}

// ---------------- launcher ----------------
extern "C" void kernel_launch(void* const* d_in, const int* in_sizes, int n_in,
                              void* d_out, int out_size) {
    const float* pred = (const float*)d_in[0];
    const float* tgt  = (const float*)d_in[1];
    const float* rw   = (const float*)d_in[2];
    float* out = (float*)d_out;

    k_init<<<1, 1024>>>();
    k_binpair<<<KCOLS, 512>>>();
    k_rowfft<<<dim3(64, NIMG), 256>>>(pred, tgt);
    k_colfft<<<dim3(65, NIMG), 256>>>();
    k_final<<<1, NIMG * NBINS>>>(rw, out);
}